// round 3
// baseline (speedup 1.0000x reference)
#include <cuda_runtime.h>
#include <cstdint>

#define CAPL   65536
#define NMSCAP 5000
#define NEGV   (-1000000000.0f)
#define BBOXCL 4.135166556742356f

typedef unsigned long long ull;

// ------------------------- device scratch (no allocs) -----------------------
__device__ float g_bufA[7782400];
__device__ float g_bufB[7782400];
__device__ float g_reg[1459224];
__device__ float g_mu[64];
__device__ float g_var[64];
__device__ ull   g_k64[10 * CAPL];
__device__ int   g_cnt[10];
__device__ float g_nbox[2 * NMSCAP * 4];

__constant__ int  c_HW[5]     = {15200, 3800, 950, 247, 70};
__constant__ long c_regoff[5] = {0, 1094400, 1368000, 1436400, 1454184};
__constant__ int  c_ancoff[5] = {0, 136800, 171000, 179550, 181773};

// ------------------------- f32x2 packed helpers -----------------------------
__device__ __forceinline__ ull pk2(float lo, float hi) {
    ull r;
    asm("mov.b64 %0, {%1, %2};" : "=l"(r) : "f"(lo), "f"(hi));
    return r;
}
__device__ __forceinline__ ull fma2(ull a, ull b, ull c) {
    ull d;
    asm("fma.rn.f32x2 %0, %1, %2, %3;" : "=l"(d) : "l"(a), "l"(b), "l"(c));
    return d;
}
__device__ __forceinline__ float2 upk(ull v) {
    float2 f;
    asm("mov.b64 {%0, %1}, %2;" : "=f"(f.x), "=f"(f.y) : "l"(v));
    return f;
}

// ------------------------- candidate emit -----------------------------------
__device__ __forceinline__ void emit_cand(float v, int oc, int s, int n, int lvl) {
    float sg = 1.0f / (1.0f + expf(-v));
    if (sg > 0.05f) {
        int a = oc / 91, c = oc - 91 * a;
        unsigned flat = (unsigned)((s * 9 + a) * 91 + c);
        unsigned key  = ((unsigned)lvl << 24) | flat;
        int pos = atomicAdd(&g_cnt[n * 5 + lvl], 1);
        if (pos < CAPL)
            g_k64[(long)(n * 5 + lvl) * CAPL + pos] =
                (((ull)(0xFFFFFFFFu - __float_as_uint(sg))) << 32) | key;
    }
}

// ------------------------- conv 3x3 SAME, Cin=256, fp32 (FFMA2) -------------
// block 256 thr: 64 oc x (8h x 16w). per thread: 4 oc x 8 px (4 f32x2 pairs).
// optional fused GN(prev stats)+ReLU on input load; optional candidate epilogue.
__global__ __launch_bounds__(256) void conv3x3(
    const float* __restrict__ xext, int xsel,
    const float* __restrict__ gs, const float* __restrict__ gb, int gnflag,
    int ysel, long yoff,
    const float* __restrict__ wgt, const float* __restrict__ bias,
    int OC, int H, int W, int octiles, int cand_level)
{
    __shared__ float xsm[1600];          // 8 ic x 10 rows x stride 20
    __shared__ ull   wsd[72 * 66];       // [ic*9+tap][oc] duplicated (w,w)
    __shared__ float scl[256], shb[256];

    const int t = threadIdx.x;
    const int n   = blockIdx.z / octiles;
    const int oc0 = (blockIdx.z % octiles) * 64;
    const int h0 = blockIdx.y * 8, w0 = blockIdx.x * 16;
    const int oc_id = t >> 4;            // 0..15 (4 oc each)
    const int px_id = t & 15;
    const int ph  = px_id >> 1;          // 0..7
    const int pw0 = (px_id & 1) * 8;     // 0 or 8

    const float* x = xext ? xext : (xsel == 0 ? g_bufA : g_bufB);

    // per-channel GN scale/shift (folded): v*scl + shb, then relu
    {
        int c = t;
        if (gnflag) {
            int b = n * 32 + (c >> 3);
            float s2 = rsqrtf(g_var[b] + 1e-5f) * gs[c];
            scl[c] = s2;
            shb[c] = gb[c] - g_mu[b] * s2;
        } else { scl[c] = 1.f; shb[c] = 0.f; }
    }
    __syncthreads();

    ull acc[4][4];
#pragma unroll
    for (int i = 0; i < 4; i++)
#pragma unroll
        for (int j = 0; j < 4; j++) acc[i][j] = 0ull;

    for (int ic0 = 0; ic0 < 256; ic0 += 8) {
        // ---- input window: 8 ic x 10h x 18w (zero pad, fused GN+ReLU) ----
        for (int d = t; d < 1440; d += 256) {
            int ic = d / 180, r = d - ic * 180;
            int iy = r / 18, ix = r - iy * 18;
            int gy = h0 - 1 + iy, gx = w0 - 1 + ix;
            float v = 0.f;
            if ((unsigned)gy < (unsigned)H && (unsigned)gx < (unsigned)W) {
                v = x[((long)(n * 256 + ic0 + ic) * H + gy) * W + gx];
                if (gnflag) v = fmaxf(v * scl[ic0 + ic] + shb[ic0 + ic], 0.f);
            }
            xsm[ic * 200 + iy * 20 + ix] = v;
        }
        // ---- weights: 64 oc x 8 ic x 9, duplicated pairs ----
        for (int d = t; d < 4608; d += 256) {
            int oc = d / 72, tap = d - oc * 72;
            int oca = oc0 + oc;
            float v = (oca < OC) ? wgt[(long)oca * 2304 + ic0 * 9 + tap] : 0.f;
            wsd[tap * 66 + oc] = pk2(v, v);
        }
        __syncthreads();

#pragma unroll 1
        for (int ic = 0; ic < 8; ic++) {
            const float* xr = xsm + ic * 200 + pw0;
            const ull* wb = wsd + ic * 9 * 66 + (oc_id << 2);
#pragma unroll
            for (int ky = 0; ky < 3; ky++) {
                const float* row = xr + (ph + ky) * 20;
                float4 a4 = *reinterpret_cast<const float4*>(row);
                float4 b4 = *reinterpret_cast<const float4*>(row + 4);
                float2 c2 = *reinterpret_cast<const float2*>(row + 8);
                ull pe0 = pk2(a4.x, a4.y);
                ull pe1 = pk2(a4.z, a4.w);
                ull pe2 = pk2(b4.x, b4.y);
                ull pe3 = pk2(b4.z, b4.w);
                ull pe4 = pk2(c2.x, c2.y);
                ull po0 = pk2(a4.y, a4.z);
                ull po1 = pk2(a4.w, b4.x);
                ull po2 = pk2(b4.y, b4.z);
                ull po3 = pk2(b4.w, c2.x);
                const ull* wr = wb + ky * 3 * 66;

#define KXSTEP(WPTR, P0, P1, P2, P3)                                           \
                {                                                              \
                    ulonglong2 wa = *reinterpret_cast<const ulonglong2*>(WPTR);\
                    ulonglong2 wc = *reinterpret_cast<const ulonglong2*>((WPTR) + 2);\
                    acc[0][0] = fma2(wa.x, P0, acc[0][0]);                     \
                    acc[0][1] = fma2(wa.x, P1, acc[0][1]);                     \
                    acc[0][2] = fma2(wa.x, P2, acc[0][2]);                     \
                    acc[0][3] = fma2(wa.x, P3, acc[0][3]);                     \
                    acc[1][0] = fma2(wa.y, P0, acc[1][0]);                     \
                    acc[1][1] = fma2(wa.y, P1, acc[1][1]);                     \
                    acc[1][2] = fma2(wa.y, P2, acc[1][2]);                     \
                    acc[1][3] = fma2(wa.y, P3, acc[1][3]);                     \
                    acc[2][0] = fma2(wc.x, P0, acc[2][0]);                     \
                    acc[2][1] = fma2(wc.x, P1, acc[2][1]);                     \
                    acc[2][2] = fma2(wc.x, P2, acc[2][2]);                     \
                    acc[2][3] = fma2(wc.x, P3, acc[2][3]);                     \
                    acc[3][0] = fma2(wc.y, P0, acc[3][0]);                     \
                    acc[3][1] = fma2(wc.y, P1, acc[3][1]);                     \
                    acc[3][2] = fma2(wc.y, P2, acc[3][2]);                     \
                    acc[3][3] = fma2(wc.y, P3, acc[3][3]);                     \
                }
                KXSTEP(wr,        pe0, pe1, pe2, pe3)   // kx = 0
                KXSTEP(wr + 66,   po0, po1, po2, po3)   // kx = 1
                KXSTEP(wr + 132,  pe1, pe2, pe3, pe4)   // kx = 2
#undef KXSTEP
            }
        }
        __syncthreads();
    }

    // ---- epilogue ----
    const int h = h0 + ph;
    const bool cand = (cand_level >= 0);
    float* y = (ysel == 0) ? g_bufA : (ysel == 1 ? g_bufB : g_reg + yoff);
    if (h < H) {
#pragma unroll
        for (int i = 0; i < 4; i++) {
            int oc = oc0 + (oc_id << 2) + i;
            if (oc < OC) {
                float bv = bias[oc];
#pragma unroll
                for (int j = 0; j < 4; j++) {
                    float2 f = upk(acc[i][j]);
                    int w1 = w0 + pw0 + 2 * j;
                    float v0 = f.x + bv, v1 = f.y + bv;
                    if (cand) {
                        if (w1 < W && v0 > -3.0f)
                            emit_cand(v0, oc, h * W + w1, n, cand_level);
                        if (w1 + 1 < W && v1 > -3.0f)
                            emit_cand(v1, oc, h * W + w1 + 1, n, cand_level);
                    } else {
                        long base = ((long)(n * OC + oc) * H + h) * W;
                        if (w1 < W)     y[base + w1]     = v0;
                        if (w1 + 1 < W) y[base + w1 + 1] = v1;
                    }
                }
            }
        }
    }
}

// ------------------------- GroupNorm stats ----------------------------------
__global__ __launch_bounds__(256) void gn_stats(int xsel, int HW)
{
    const int b = blockIdx.x;                 // n*32+g
    const int n = b >> 5, g = b & 31;
    const float* p = (xsel == 0 ? g_bufA : g_bufB) + (long)(n * 256 + g * 8) * HW;
    const int total = 8 * HW;
    double s = 0.0, ss = 0.0;
    for (int i = threadIdx.x; i < total; i += 256) {
        float v = p[i];
        s += v; ss += (double)v * (double)v;
    }
    __shared__ double rs[256], rq[256];
    rs[threadIdx.x] = s; rq[threadIdx.x] = ss;
    __syncthreads();
    for (int o = 128; o; o >>= 1) {
        if (threadIdx.x < o) { rs[threadIdx.x] += rs[threadIdx.x+o]; rq[threadIdx.x] += rq[threadIdx.x+o]; }
        __syncthreads();
    }
    if (threadIdx.x == 0) {
        double mu = rs[0] / total;
        g_mu[b]  = (float)mu;
        g_var[b] = (float)(rq[0] / total - mu * mu);
    }
}

// ------------------------- sort / nms ----------------------------------------
__global__ void zero_cnt() { if (threadIdx.x < 10) g_cnt[threadIdx.x] = 0; }

__global__ __launch_bounds__(1024) void sort_k()
{
    const int b = blockIdx.x;
    ull* v = g_k64 + (long)b * CAPL;
    int cnt = g_cnt[b]; if (cnt > CAPL) cnt = CAPL;
    if (cnt <= 1) return;
    int n2 = 1; while (n2 < cnt) n2 <<= 1;
    for (int i = cnt + threadIdx.x; i < n2; i += 1024) v[i] = ~0ull;
    __syncthreads();
    for (int k = 2; k <= n2; k <<= 1) {
        for (int j = k >> 1; j > 0; j >>= 1) {
            for (int i = threadIdx.x; i < n2; i += 1024) {
                int ixj = i ^ j;
                if (ixj > i) {
                    ull a = v[i], c2 = v[ixj];
                    if ((a > c2) == ((i & k) == 0)) { v[i] = c2; v[ixj] = a; }
                }
            }
            __syncthreads();
        }
    }
}

extern __shared__ unsigned char s_raw[];

__global__ __launch_bounds__(256) void nms_k(const float* __restrict__ anc,
                                             float* __restrict__ out)
{
    const int n = blockIdx.x;
    float*    sws  = (float*)s_raw;
    float*    sbo  = (float*)s_raw + 5008;
    unsigned* skey = (unsigned*)((float*)s_raw + 25008);
    __shared__ float rbs[256];
    __shared__ unsigned rbk[256];
    __shared__ int rbi[256];

    int Ls[5], offs[5], K = 0;
    for (int l = 0; l < 5; l++) {
        int c = g_cnt[n * 5 + l];
        if (c > CAPL) c = CAPL;
        if (c > 1000) c = 1000;
        offs[l] = K; Ls[l] = c; K += c;
    }

    for (int idx = threadIdx.x; idx < K; idx += 256) {
        int l = 0;
        while (l < 4 && idx >= offs[l] + Ls[l]) l++;
        int kin = idx - offs[l];
        ull v = g_k64[(long)(n * 5 + l) * CAPL + kin];
        unsigned key = (unsigned)v;
        float sc = __uint_as_float(0xFFFFFFFFu - (unsigned)(v >> 32));
        int flat = (int)(key & 0xFFFFFFu);
        int ai = flat / 91, c = flat - ai * 91;
        int sidx = ai / 9, a = ai - sidx * 9;
        int HW = c_HW[l];
        const float* rp = g_reg + c_regoff[l] + (long)(n * 36 + a * 4) * HW + sidx;
        float dx = rp[0], dy = rp[HW], dw = rp[2*HW], dh = rp[3*HW];
        int gidx = c_ancoff[l] + ai;
        float ax0 = anc[4*gidx], ay0 = anc[4*gidx+1], ax1 = anc[4*gidx+2], ay1 = anc[4*gidx+3];
        float aw = ax1 - ax0, ah = ay1 - ay0;
        float cx = ax0 + 0.5f * aw, cy = ay0 + 0.5f * ah;
        dw = fminf(dw, BBOXCL); dh = fminf(dh, BBOXCL);
        float pcx = dx * aw + cx, pcy = dy * ah + cy;
        float pw = expf(dw) * aw, phh = expf(dh) * ah;
        float b0 = fminf(fmaxf(pcx - 0.5f*pw , 0.f), 1216.f);
        float b1 = fminf(fmaxf(pcy - 0.5f*phh, 0.f),  800.f);
        float b2 = fminf(fmaxf(pcx + 0.5f*pw , 0.f), 1216.f);
        float b3 = fminf(fmaxf(pcy + 0.5f*phh, 0.f),  800.f);
        float* nb = &g_nbox[(n * NMSCAP + idx) * 4];
        nb[0]=b0; nb[1]=b1; nb[2]=b2; nb[3]=b3;
        float off = (float)c * 2017.0f;
        sbo[idx*4+0]=b0+off; sbo[idx*4+1]=b1+off; sbo[idx*4+2]=b2+off; sbo[idx*4+3]=b3+off;
        sws[idx] = sc; skey[idx] = key;
    }
    __syncthreads();

    int m = 0;
    for (; m < 300; m++) {
        float bs = -1e30f; unsigned bk = 0xFFFFFFFFu; int bi = -1;
        for (int k = threadIdx.x; k < K; k += 256) {
            float s = sws[k];
            if (s > bs || (s == bs && skey[k] < bk)) { bs = s; bk = skey[k]; bi = k; }
        }
        rbs[threadIdx.x]=bs; rbk[threadIdx.x]=bk; rbi[threadIdx.x]=bi;
        __syncthreads();
        for (int o = 128; o; o >>= 1) {
            if (threadIdx.x < o) {
                float s2 = rbs[threadIdx.x+o];
                if (s2 > rbs[threadIdx.x] ||
                    (s2 == rbs[threadIdx.x] && rbk[threadIdx.x+o] < rbk[threadIdx.x])) {
                    rbs[threadIdx.x]=s2; rbk[threadIdx.x]=rbk[threadIdx.x+o]; rbi[threadIdx.x]=rbi[threadIdx.x+o];
                }
            }
            __syncthreads();
        }
        bs = rbs[0]; bi = rbi[0]; bk = rbk[0];
        if (bs <= 0.0f) break;
        if (threadIdx.x == 0) {
            float* nb = &g_nbox[(n * NMSCAP + bi) * 4];
            out[n*1200 + m*4+0]=nb[0]; out[n*1200 + m*4+1]=nb[1];
            out[n*1200 + m*4+2]=nb[2]; out[n*1200 + m*4+3]=nb[3];
            out[2400 + n*300 + m] = bs;
            out[3000 + n*300 + m] = (float)((bk & 0xFFFFFFu) % 91u);
        }
        float jb0=sbo[bi*4+0], jb1=sbo[bi*4+1], jb2=sbo[bi*4+2], jb3=sbo[bi*4+3];
        float ja = (jb2-jb0)*(jb3-jb1);
        for (int k = threadIdx.x; k < K; k += 256) {
            float x0 = fmaxf(jb0, sbo[k*4+0]);
            float y0 = fmaxf(jb1, sbo[k*4+1]);
            float x1 = fminf(jb2, sbo[k*4+2]);
            float y1 = fminf(jb3, sbo[k*4+3]);
            float iw = fmaxf(x1-x0, 0.f), ih = fmaxf(y1-y0, 0.f);
            float inter = iw*ih;
            float a2 = (sbo[k*4+2]-sbo[k*4+0])*(sbo[k*4+3]-sbo[k*4+1]);
            if (inter / (ja + a2 - inter + 1e-9f) > 0.5f) sws[k] = NEGV;
        }
        __syncthreads();
    }
    for (int slot = m + (int)threadIdx.x; slot < 300; slot += 256) {
        out[n*1200 + slot*4+0]=0.f; out[n*1200 + slot*4+1]=0.f;
        out[n*1200 + slot*4+2]=0.f; out[n*1200 + slot*4+3]=0.f;
        out[2400 + n*300 + slot] = 0.f;
        out[3000 + n*300 + slot] = -1.f;
    }
}

// ------------------------- host ----------------------------------------------
extern "C" void kernel_launch(void* const* d_in, const int* in_sizes, int n_in,
                              void* d_out, int out_size)
{
    const float* feats[5];
    for (int i = 0; i < 5; i++) feats[i] = (const float*)d_in[i];
    const float* cls_tw = (const float*)d_in[5];
    const float* cls_tb = (const float*)d_in[6];
    const float* cls_gs = (const float*)d_in[7];
    const float* cls_gb = (const float*)d_in[8];
    const float* cls_w  = (const float*)d_in[9];
    const float* cls_b  = (const float*)d_in[10];
    const float* reg_tw = (const float*)d_in[11];
    const float* reg_tb = (const float*)d_in[12];
    const float* reg_gs = (const float*)d_in[13];
    const float* reg_gb = (const float*)d_in[14];
    const float* reg_w  = (const float*)d_in[15];
    const float* reg_b  = (const float*)d_in[16];
    const float* anchors = (const float*)d_in[17];
    float* out = (float*)d_out;

    static const int  Hs[5] = {100, 50, 25, 13, 7};
    static const int  Ws[5] = {152, 76, 38, 19, 10};
    static const long regoff[5] = {0, 1094400, 1368000, 1436400, 1454184};
    const long TW1 = 589824; // 256*256*9

    cudaFuncSetAttribute(nms_k, cudaFuncAttributeMaxDynamicSharedMemorySize, 122880);

    zero_cnt<<<1, 32>>>();

    for (int l = 0; l < 5; l++) {
        int H = Hs[l], W = Ws[l], HW = H * W;
        dim3 gt((W + 15) / 16, (H + 7) / 8, 2 * 4);

        for (int br = 0; br < 2; br++) {
            const float* tw = br ? reg_tw : cls_tw;
            const float* tb = br ? reg_tb : cls_tb;
            const float* tgs = br ? reg_gs : cls_gs;
            const float* tgb = br ? reg_gb : cls_gb;

            conv3x3<<<gt, 256>>>(feats[l], 0, nullptr, nullptr, 0,
                                 0, 0, tw, tb, 256, H, W, 4, -1);
            gn_stats<<<64, 256>>>(0, HW);
            conv3x3<<<gt, 256>>>(nullptr, 0, tgs, tgb, 1,
                                 1, 0, tw + TW1, tb + 256, 256, H, W, 4, -1);
            gn_stats<<<64, 256>>>(1, HW);
            conv3x3<<<gt, 256>>>(nullptr, 1, tgs + 256, tgb + 256, 1,
                                 0, 0, tw + 2 * TW1, tb + 512, 256, H, W, 4, -1);
            gn_stats<<<64, 256>>>(0, HW);
            conv3x3<<<gt, 256>>>(nullptr, 0, tgs + 512, tgb + 512, 1,
                                 1, 0, tw + 3 * TW1, tb + 768, 256, H, W, 4, -1);
            gn_stats<<<64, 256>>>(1, HW);

            if (br == 0) {
                dim3 gc((W + 15) / 16, (H + 7) / 8, 2 * 13);
                conv3x3<<<gc, 256>>>(nullptr, 1, tgs + 768, tgb + 768, 1,
                                     3, 0, cls_w, cls_b, 819, H, W, 13, l);
            } else {
                dim3 gr((W + 15) / 16, (H + 7) / 8, 2 * 1);
                conv3x3<<<gr, 256>>>(nullptr, 1, tgs + 768, tgb + 768, 1,
                                     3, regoff[l], reg_w, reg_b, 36, H, W, 1, -1);
            }
        }
    }

    sort_k<<<10, 1024>>>();
    nms_k<<<2, 256, 122880>>>(anchors, out);
}

// round 4
// speedup vs baseline: 1.5186x; 1.5186x over previous
#include <cuda_runtime.h>
#include <cstdint>

#define CAPL   65536
#define NMSCAP 5000
#define NEGV   (-1000000000.0f)
#define BBOXCL 4.135166556742356f

typedef unsigned long long ull;

// ------------------------- device scratch (no allocs) -----------------------
// merged activation buffers: [2 branch][2 pingpong], each holds all 5 levels
// level base (floats): 512 * prefixHW ; total 20267*512 = 10376704 floats
__device__ float g_t0[10376704];
__device__ float g_t1[10376704];
__device__ float g_t2[10376704];
__device__ float g_t3[10376704];
__device__ float g_reg[1459224];
__device__ float g_mu[640];
__device__ float g_var[640];
__device__ ull   g_k64[10 * CAPL];
__device__ int   g_cnt[10];
__device__ float g_nbox[2 * NMSCAP * 4];

__constant__ int  c_Hs[5]    = {100, 50, 25, 13, 7};
__constant__ int  c_Ws[5]    = {152, 76, 38, 19, 10};
__constant__ int  c_HW[5]    = {15200, 3800, 950, 247, 70};
__constant__ long c_lb[5]    = {0, 7782400, 9728000, 10214400, 10340864};
__constant__ long c_regoff[5] = {0, 1094400, 1368000, 1436400, 1454184};
__constant__ int  c_ancoff[5] = {0, 136800, 171000, 179550, 181773};
__constant__ int  c_cum[5]   = {247, 317, 337, 343, 345};   // cumulative 8x8 tiles
__constant__ int  c_tw[5]    = {19, 10, 5, 3, 2};           // tiles along W

__device__ __forceinline__ float* tb(int id) {
    switch (id) {
        case 0: return g_t0;
        case 1: return g_t1;
        case 2: return g_t2;
        default: return g_t3;
    }
}

// ------------------------- candidate emit -----------------------------------
__device__ __forceinline__ void emit_cand(float v, int oc, int s, int n, int lvl) {
    float sg = 1.0f / (1.0f + expf(-v));
    if (sg > 0.05f) {
        int a = oc / 91, c = oc - 91 * a;
        unsigned flat = (unsigned)((s * 9 + a) * 91 + c);
        unsigned key  = ((unsigned)lvl << 24) | flat;
        int pos = atomicAdd(&g_cnt[n * 5 + lvl], 1);
        if (pos < CAPL)
            g_k64[(long)(n * 5 + lvl) * CAPL + pos] =
                (((ull)(0xFFFFFFFFu - __float_as_uint(sg))) << 32) | key;
    }
}

// ------------------------- merged conv 3x3 SAME, Cin=256, fp32 --------------
// one launch covers all 5 levels (x both images x both branches).
// block 256 thr = 64 oc x (8x8 px); per-thread 4 oc x 4 px. (R2-proven mainloop)
// ymode: 0 = tower write, 1 = cls candidate emit, 2 = reg-head write
__global__ __launch_bounds__(256) void conv_m(
    const float* __restrict__ x0, const float* __restrict__ x1,
    const float* __restrict__ x2, const float* __restrict__ x3,
    const float* __restrict__ x4,
    int xpp, int ymode, int ypp,
    const float* __restrict__ wA, const float* __restrict__ wB,
    const float* __restrict__ bA, const float* __restrict__ bB,
    const float* __restrict__ gsA, const float* __restrict__ gbA,
    const float* __restrict__ gsB, const float* __restrict__ gbB,
    int gnflag, int OC, int OCT, int NBR, int brfix)
{
    __shared__ float xs[16 * 110];                 // 16 ic x 10x10 (stride 11)
    __shared__ __align__(16) float ws[144 * 68];   // [ic*9+tap][oc]
    __shared__ float scl[256], shb[256];

    // ---- block decomposition: oct fastest (adjacent blocks share x-window) --
    int bid = blockIdx.x;
    const int oct = bid % OCT;  bid /= OCT;
    const int tile = bid % 345; bid /= 345;
    const int n = bid % 2;      bid /= 2;
    const int br = (NBR == 2) ? bid : brfix;

    int l = 0;
    while (tile >= c_cum[l]) l++;
    const int ltile = tile - (l ? c_cum[l - 1] : 0);
    const int H = c_Hs[l], W = c_Ws[l], HW = c_HW[l];
    const int h0 = (ltile / c_tw[l]) * 8;
    const int w0 = (ltile % c_tw[l]) * 8;
    const int oc0 = oct * 64;

    const float* wgt = br ? wB : wA;
    const float* bias = br ? bB : bA;

    const float* x;
    if (xpp < 0) {
        x = (l == 0) ? x0 : (l == 1) ? x1 : (l == 2) ? x2 : (l == 3) ? x3 : x4;
    } else {
        x = tb(br * 2 + xpp) + c_lb[l];
    }

    const int t = threadIdx.x;
    const int oc_id = t >> 4;            // 0..15 (4 oc each)
    const int px_id = t & 15;
    const int ph  = px_id >> 1;          // 0..7
    const int pw0 = (px_id & 1) * 4;     // 0 or 4

    // per-channel folded GN scale/shift: v*scl + shb, then relu (on input load)
    {
        const int c = t;
        if (gnflag) {
            const float* gs = br ? gsB : gsA;
            const float* gb = br ? gbB : gbA;
            int m = ((br * 5 + l) * 2 + n) * 32 + (c >> 3);
            float s2 = rsqrtf(g_var[m] + 1e-5f) * gs[c];
            scl[c] = s2;
            shb[c] = gb[c] - g_mu[m] * s2;
        } else { scl[c] = 1.f; shb[c] = 0.f; }
    }
    __syncthreads();

    float acc[4][4] = {};

    for (int ic0 = 0; ic0 < 256; ic0 += 16) {
        // ---- input window: 16 ic x 10x10, zero pad, fused GN+ReLU ----
        for (int d = t; d < 1600; d += 256) {
            int ic = d / 100, r = d - ic * 100;
            int iy = r / 10, ix = r - iy * 10;
            int gy = h0 - 1 + iy, gx = w0 - 1 + ix;
            float v = 0.f;
            if ((unsigned)gy < (unsigned)H && (unsigned)gx < (unsigned)W) {
                v = x[(long)(n * 256 + ic0 + ic) * HW + gy * W + gx];
                if (gnflag) v = fmaxf(v * scl[ic0 + ic] + shb[ic0 + ic], 0.f);
            }
            xs[ic * 110 + iy * 11 + ix] = v;
        }
        // ---- weights: 64 oc x 16 ic x 9 ----
        for (int d = t; d < 9216; d += 256) {
            int oc = d / 144, r = d - oc * 144;
            int oca = oc0 + oc;
            float v = 0.f;
            if (oca < OC) v = wgt[((long)oca * 256 + ic0) * 9 + r];
            ws[r * 68 + oc] = v;
        }
        __syncthreads();

#pragma unroll 4
        for (int ic = 0; ic < 16; ic++) {
#pragma unroll
            for (int ky = 0; ky < 3; ky++) {
                float xv[6];
#pragma unroll
                for (int j = 0; j < 6; j++)
                    xv[j] = xs[ic * 110 + (ph + ky) * 11 + pw0 + j];
#pragma unroll
                for (int kx = 0; kx < 3; kx++) {
                    const float4 wv = *reinterpret_cast<const float4*>(
                        &ws[(ic * 9 + ky * 3 + kx) * 68 + (oc_id << 2)]);
#pragma unroll
                    for (int j = 0; j < 4; j++) {
                        acc[0][j] += wv.x * xv[kx + j];
                        acc[1][j] += wv.y * xv[kx + j];
                        acc[2][j] += wv.z * xv[kx + j];
                        acc[3][j] += wv.w * xv[kx + j];
                    }
                }
            }
        }
        __syncthreads();
    }

    // ---- epilogue ----
    const int h = h0 + ph;
    if (h < H) {
        float* y = (ymode == 0) ? tb(br * 2 + ypp) + c_lb[l]
                 : (ymode == 2) ? g_reg + c_regoff[l] : nullptr;
#pragma unroll
        for (int i = 0; i < 4; i++) {
            int oc = oc0 + (oc_id << 2) + i;
            if (oc < OC) {
                float bv = bias[oc];
#pragma unroll
                for (int j = 0; j < 4; j++) {
                    int w = w0 + pw0 + j;
                    if (w < W) {
                        float v = acc[i][j] + bv;
                        if (ymode == 1) {
                            if (v > -3.0f) emit_cand(v, oc, h * W + w, n, l);
                        } else if (ymode == 0) {
                            y[(long)(n * 256 + oc) * HW + h * W + w] = v;
                        } else {
                            y[(long)(n * 36 + oc) * HW + h * W + w] = v;
                        }
                    }
                }
            }
        }
    }
}

// ------------------------- merged GroupNorm stats ---------------------------
// grid: 2br x 5lvl x 2n x 32g = 640 blocks
__global__ __launch_bounds__(256) void gn_stats_m(int pp)
{
    int b = blockIdx.x;
    const int g = b % 32; b /= 32;
    const int n = b % 2;  b /= 2;
    const int l = b % 5;  b /= 5;
    const int br = b;
    const int HW = c_HW[l];
    const float* p = tb(br * 2 + pp) + c_lb[l] + (long)(n * 256 + g * 8) * HW;
    const int total = 8 * HW;
    double s = 0.0, ss = 0.0;
    for (int i = threadIdx.x; i < total; i += 256) {
        float v = p[i];
        s += v; ss += (double)v * (double)v;
    }
    __shared__ double rs[256], rq[256];
    rs[threadIdx.x] = s; rq[threadIdx.x] = ss;
    __syncthreads();
    for (int o = 128; o; o >>= 1) {
        if (threadIdx.x < o) { rs[threadIdx.x] += rs[threadIdx.x+o]; rq[threadIdx.x] += rq[threadIdx.x+o]; }
        __syncthreads();
    }
    if (threadIdx.x == 0) {
        int m = ((br * 5 + l) * 2 + n) * 32 + g;
        double mu = rs[0] / total;
        g_mu[m]  = (float)mu;
        g_var[m] = (float)(rq[0] / total - mu * mu);
    }
}

// ------------------------- sort / nms ----------------------------------------
__global__ void zero_cnt() { if (threadIdx.x < 10) g_cnt[threadIdx.x] = 0; }

__global__ __launch_bounds__(1024) void sort_k()
{
    const int b = blockIdx.x;
    ull* v = g_k64 + (long)b * CAPL;
    int cnt = g_cnt[b]; if (cnt > CAPL) cnt = CAPL;
    if (cnt <= 1) return;
    int n2 = 1; while (n2 < cnt) n2 <<= 1;
    for (int i = cnt + threadIdx.x; i < n2; i += 1024) v[i] = ~0ull;
    __syncthreads();
    for (int k = 2; k <= n2; k <<= 1) {
        for (int j = k >> 1; j > 0; j >>= 1) {
            for (int i = threadIdx.x; i < n2; i += 1024) {
                int ixj = i ^ j;
                if (ixj > i) {
                    ull a = v[i], c2 = v[ixj];
                    if ((a > c2) == ((i & k) == 0)) { v[i] = c2; v[ixj] = a; }
                }
            }
            __syncthreads();
        }
    }
}

extern __shared__ unsigned char s_raw[];

__global__ __launch_bounds__(256) void nms_k(const float* __restrict__ anc,
                                             float* __restrict__ out)
{
    const int n = blockIdx.x;
    float*    sws  = (float*)s_raw;
    float*    sbo  = (float*)s_raw + 5008;
    unsigned* skey = (unsigned*)((float*)s_raw + 25008);
    __shared__ float rbs[256];
    __shared__ unsigned rbk[256];
    __shared__ int rbi[256];

    int Ls[5], offs[5], K = 0;
    for (int l = 0; l < 5; l++) {
        int c = g_cnt[n * 5 + l];
        if (c > CAPL) c = CAPL;
        if (c > 1000) c = 1000;
        offs[l] = K; Ls[l] = c; K += c;
    }

    for (int idx = threadIdx.x; idx < K; idx += 256) {
        int l = 0;
        while (l < 4 && idx >= offs[l] + Ls[l]) l++;
        int kin = idx - offs[l];
        ull v = g_k64[(long)(n * 5 + l) * CAPL + kin];
        unsigned key = (unsigned)v;
        float sc = __uint_as_float(0xFFFFFFFFu - (unsigned)(v >> 32));
        int flat = (int)(key & 0xFFFFFFu);
        int ai = flat / 91, c = flat - ai * 91;
        int sidx = ai / 9, a = ai - sidx * 9;
        int HW = c_HW[l];
        const float* rp = g_reg + c_regoff[l] + (long)(n * 36 + a * 4) * HW + sidx;
        float dx = rp[0], dy = rp[HW], dw = rp[2*HW], dh = rp[3*HW];
        int gidx = c_ancoff[l] + ai;
        float ax0 = anc[4*gidx], ay0 = anc[4*gidx+1], ax1 = anc[4*gidx+2], ay1 = anc[4*gidx+3];
        float aw = ax1 - ax0, ah = ay1 - ay0;
        float cx = ax0 + 0.5f * aw, cy = ay0 + 0.5f * ah;
        dw = fminf(dw, BBOXCL); dh = fminf(dh, BBOXCL);
        float pcx = dx * aw + cx, pcy = dy * ah + cy;
        float pw = expf(dw) * aw, phh = expf(dh) * ah;
        float b0 = fminf(fmaxf(pcx - 0.5f*pw , 0.f), 1216.f);
        float b1 = fminf(fmaxf(pcy - 0.5f*phh, 0.f),  800.f);
        float b2 = fminf(fmaxf(pcx + 0.5f*pw , 0.f), 1216.f);
        float b3 = fminf(fmaxf(pcy + 0.5f*phh, 0.f),  800.f);
        float* nb = &g_nbox[(n * NMSCAP + idx) * 4];
        nb[0]=b0; nb[1]=b1; nb[2]=b2; nb[3]=b3;
        float off = (float)c * 2017.0f;
        sbo[idx*4+0]=b0+off; sbo[idx*4+1]=b1+off; sbo[idx*4+2]=b2+off; sbo[idx*4+3]=b3+off;
        sws[idx] = sc; skey[idx] = key;
    }
    __syncthreads();

    int m = 0;
    for (; m < 300; m++) {
        float bs = -1e30f; unsigned bk = 0xFFFFFFFFu; int bi = -1;
        for (int k = threadIdx.x; k < K; k += 256) {
            float s = sws[k];
            if (s > bs || (s == bs && skey[k] < bk)) { bs = s; bk = skey[k]; bi = k; }
        }
        rbs[threadIdx.x]=bs; rbk[threadIdx.x]=bk; rbi[threadIdx.x]=bi;
        __syncthreads();
        for (int o = 128; o; o >>= 1) {
            if (threadIdx.x < o) {
                float s2 = rbs[threadIdx.x+o];
                if (s2 > rbs[threadIdx.x] ||
                    (s2 == rbs[threadIdx.x] && rbk[threadIdx.x+o] < rbk[threadIdx.x])) {
                    rbs[threadIdx.x]=s2; rbk[threadIdx.x]=rbk[threadIdx.x+o]; rbi[threadIdx.x]=rbi[threadIdx.x+o];
                }
            }
            __syncthreads();
        }
        bs = rbs[0]; bi = rbi[0]; bk = rbk[0];
        if (bs <= 0.0f) break;
        if (threadIdx.x == 0) {
            float* nb = &g_nbox[(n * NMSCAP + bi) * 4];
            out[n*1200 + m*4+0]=nb[0]; out[n*1200 + m*4+1]=nb[1];
            out[n*1200 + m*4+2]=nb[2]; out[n*1200 + m*4+3]=nb[3];
            out[2400 + n*300 + m] = bs;
            out[3000 + n*300 + m] = (float)((bk & 0xFFFFFFu) % 91u);
        }
        float jb0=sbo[bi*4+0], jb1=sbo[bi*4+1], jb2=sbo[bi*4+2], jb3=sbo[bi*4+3];
        float ja = (jb2-jb0)*(jb3-jb1);
        for (int k = threadIdx.x; k < K; k += 256) {
            float x0 = fmaxf(jb0, sbo[k*4+0]);
            float y0 = fmaxf(jb1, sbo[k*4+1]);
            float x1 = fminf(jb2, sbo[k*4+2]);
            float y1 = fminf(jb3, sbo[k*4+3]);
            float iw = fmaxf(x1-x0, 0.f), ih = fmaxf(y1-y0, 0.f);
            float inter = iw*ih;
            float a2 = (sbo[k*4+2]-sbo[k*4+0])*(sbo[k*4+3]-sbo[k*4+1]);
            if (inter / (ja + a2 - inter + 1e-9f) > 0.5f) sws[k] = NEGV;
        }
        __syncthreads();
    }
    for (int slot = m + (int)threadIdx.x; slot < 300; slot += 256) {
        out[n*1200 + slot*4+0]=0.f; out[n*1200 + slot*4+1]=0.f;
        out[n*1200 + slot*4+2]=0.f; out[n*1200 + slot*4+3]=0.f;
        out[2400 + n*300 + slot] = 0.f;
        out[3000 + n*300 + slot] = -1.f;
    }
}

// ------------------------- host ----------------------------------------------
extern "C" void kernel_launch(void* const* d_in, const int* in_sizes, int n_in,
                              void* d_out, int out_size)
{
    const float* f0 = (const float*)d_in[0];
    const float* f1 = (const float*)d_in[1];
    const float* f2 = (const float*)d_in[2];
    const float* f3 = (const float*)d_in[3];
    const float* f4 = (const float*)d_in[4];
    const float* cls_tw = (const float*)d_in[5];
    const float* cls_tb = (const float*)d_in[6];
    const float* cls_gs = (const float*)d_in[7];
    const float* cls_gb = (const float*)d_in[8];
    const float* cls_w  = (const float*)d_in[9];
    const float* cls_b  = (const float*)d_in[10];
    const float* reg_tw = (const float*)d_in[11];
    const float* reg_tb = (const float*)d_in[12];
    const float* reg_gs = (const float*)d_in[13];
    const float* reg_gb = (const float*)d_in[14];
    const float* reg_w  = (const float*)d_in[15];
    const float* reg_b  = (const float*)d_in[16];
    const float* anchors = (const float*)d_in[17];
    float* out = (float*)d_out;

    const long TW1 = 589824; // 256*256*9
    cudaFuncSetAttribute(nms_k, cudaFuncAttributeMaxDynamicSharedMemorySize, 122880);

    zero_cnt<<<1, 32>>>();

    const int GT = 345 * 2 * 4 * 2;   // towers: tiles * n * octiles * branches

    // layer 0: ext feats -> pp0 (no GN on input)
    conv_m<<<GT, 256>>>(f0, f1, f2, f3, f4, -1, 0, 0,
                        cls_tw, reg_tw, cls_tb, reg_tb,
                        nullptr, nullptr, nullptr, nullptr,
                        0, 256, 4, 2, 0);
    gn_stats_m<<<640, 256>>>(0);
    // layer 1: pp0 -> pp1, GN(layer0 params)
    conv_m<<<GT, 256>>>(nullptr, nullptr, nullptr, nullptr, nullptr, 0, 0, 1,
                        cls_tw + TW1, reg_tw + TW1, cls_tb + 256, reg_tb + 256,
                        cls_gs, cls_gb, reg_gs, reg_gb,
                        1, 256, 4, 2, 0);
    gn_stats_m<<<640, 256>>>(1);
    // layer 2: pp1 -> pp0
    conv_m<<<GT, 256>>>(nullptr, nullptr, nullptr, nullptr, nullptr, 1, 0, 0,
                        cls_tw + 2*TW1, reg_tw + 2*TW1, cls_tb + 512, reg_tb + 512,
                        cls_gs + 256, cls_gb + 256, reg_gs + 256, reg_gb + 256,
                        1, 256, 4, 2, 0);
    gn_stats_m<<<640, 256>>>(0);
    // layer 3: pp0 -> pp1
    conv_m<<<GT, 256>>>(nullptr, nullptr, nullptr, nullptr, nullptr, 0, 0, 1,
                        cls_tw + 3*TW1, reg_tw + 3*TW1, cls_tb + 768, reg_tb + 768,
                        cls_gs + 512, cls_gb + 512, reg_gs + 512, reg_gb + 512,
                        1, 256, 4, 2, 0);
    gn_stats_m<<<640, 256>>>(1);

    // cls head: pp1 -> candidate emission (GN layer3 params), br=0, OCT=13
    conv_m<<<345 * 2 * 13, 256>>>(nullptr, nullptr, nullptr, nullptr, nullptr, 1, 1, 0,
                        cls_w, cls_w, cls_b, cls_b,
                        cls_gs + 768, cls_gb + 768, cls_gs + 768, cls_gb + 768,
                        1, 819, 13, 1, 0);
    // reg head: pp1 -> g_reg, br=1, OCT=1
    conv_m<<<345 * 2 * 1, 256>>>(nullptr, nullptr, nullptr, nullptr, nullptr, 1, 2, 0,
                        reg_w, reg_w, reg_b, reg_b,
                        reg_gs + 768, reg_gb + 768, reg_gs + 768, reg_gb + 768,
                        1, 36, 1, 1, 1);

    sort_k<<<10, 1024>>>();
    nms_k<<<2, 256, 122880>>>(anchors, out);
}

// round 5
// speedup vs baseline: 1.6657x; 1.0969x over previous
#include <cuda_runtime.h>
#include <cstdint>

#define CAPL   65536
#define NMSCAP 5000
#define NEGV   (-1000000000.0f)
#define BBOXCL 4.135166556742356f

typedef unsigned long long ull;

// ------------------------- device scratch (no allocs) -----------------------
__device__ float g_t0[10376704];
__device__ float g_t1[10376704];
__device__ float g_t2[10376704];
__device__ float g_t3[10376704];
__device__ float g_reg[1459224];
__device__ float g_mu[640];
__device__ float g_var[640];
__device__ ull   g_k64[10 * CAPL];
__device__ int   g_cnt[10];
__device__ float g_nbox[2 * NMSCAP * 4];

__constant__ int  c_Hs[5]    = {100, 50, 25, 13, 7};
__constant__ int  c_Ws[5]    = {152, 76, 38, 19, 10};
__constant__ int  c_HW[5]    = {15200, 3800, 950, 247, 70};
__constant__ long c_lb[5]    = {0, 7782400, 9728000, 10214400, 10340864};
__constant__ long c_regoff[5] = {0, 1094400, 1368000, 1436400, 1454184};
__constant__ int  c_ancoff[5] = {0, 136800, 171000, 179550, 181773};
__constant__ int  c_cum[5]   = {247, 317, 337, 343, 345};
__constant__ int  c_tw[5]    = {19, 10, 5, 3, 2};

__device__ __forceinline__ float* tb(int id) {
    switch (id) {
        case 0: return g_t0;
        case 1: return g_t1;
        case 2: return g_t2;
        default: return g_t3;
    }
}

// ------------------------- candidate emit -----------------------------------
__device__ __forceinline__ void emit_cand(float v, int oc, int s, int n, int lvl) {
    float sg = 1.0f / (1.0f + expf(-v));
    if (sg > 0.05f) {
        int a = oc / 91, c = oc - 91 * a;
        unsigned flat = (unsigned)((s * 9 + a) * 91 + c);
        unsigned key  = ((unsigned)lvl << 24) | flat;
        int pos = atomicAdd(&g_cnt[n * 5 + lvl], 1);
        if (pos < CAPL)
            g_k64[(long)(n * 5 + lvl) * CAPL + pos] =
                (((ull)(0xFFFFFFFFu - __float_as_uint(sg))) << 32) | key;
    }
}

// ------------------------- merged conv 3x3 SAME, Cin=256, fp32 --------------
// block 256 thr = 64 oc x (8x8 px); per-thread 4 oc x 4 px.
// ymode: 0 = tower write, 1 = cls candidate emit, 2 = reg-head write
__global__ __launch_bounds__(256, 4) void conv_m(
    const float* __restrict__ x0, const float* __restrict__ x1,
    const float* __restrict__ x2, const float* __restrict__ x3,
    const float* __restrict__ x4,
    int xpp, int ymode, int ypp,
    const float* __restrict__ wA, const float* __restrict__ wB,
    const float* __restrict__ bA, const float* __restrict__ bB,
    const float* __restrict__ gsA, const float* __restrict__ gbA,
    const float* __restrict__ gsB, const float* __restrict__ gbB,
    int gnflag, int OC, int OCT, int NBR, int brfix)
{
    __shared__ float xs[16 * 120];                 // 16 ic x 10 rows (stride 12)
    __shared__ __align__(16) float ws[144 * 68];   // [ic*9+tap][oc]
    __shared__ float scl[256], shb[256];

    // ---- block decomposition: oct fastest ----
    int bid = blockIdx.x;
    const int oct = bid % OCT;  bid /= OCT;
    const int tile = bid % 345; bid /= 345;
    const int n = bid % 2;      bid /= 2;
    const int br = (NBR == 2) ? bid : brfix;

    int l = 0;
    while (tile >= c_cum[l]) l++;
    const int ltile = tile - (l ? c_cum[l - 1] : 0);
    const int H = c_Hs[l], W = c_Ws[l], HW = c_HW[l];
    const int h0 = (ltile / c_tw[l]) * 8;
    const int w0 = (ltile % c_tw[l]) * 8;
    const int oc0 = oct * 64;

    const float* wgt = br ? wB : wA;
    const float* bias = br ? bB : bA;

    const float* x;
    if (xpp < 0) {
        x = (l == 0) ? x0 : (l == 1) ? x1 : (l == 2) ? x2 : (l == 3) ? x3 : x4;
    } else {
        x = tb(br * 2 + xpp) + c_lb[l];
    }

    const int t = threadIdx.x;
    const int oc_id = t >> 4;            // 0..15 (4 oc each)
    const int px_id = t & 15;
    const int ph  = px_id >> 1;          // 0..7
    const int pw0 = (px_id & 1) * 4;     // 0 or 4

    // weight staging decomposition (div-free)
    const int woc = t >> 2;              // 0..63
    const int wq  = t & 3;               // 0..3 -> taps [wq*36, wq*36+36)

    // per-channel folded GN scale/shift
    {
        const int c = t;
        if (gnflag) {
            const float* gs = br ? gsB : gsA;
            const float* gb = br ? gbB : gbA;
            int m = ((br * 5 + l) * 2 + n) * 32 + (c >> 3);
            float s2 = rsqrtf(g_var[m] + 1e-5f) * gs[c];
            scl[c] = s2;
            shb[c] = gb[c] - g_mu[m] * s2;
        } else { scl[c] = 1.f; shb[c] = 0.f; }
    }
    __syncthreads();

    float acc[4][4] = {};

    for (int ic0 = 0; ic0 < 256; ic0 += 16) {
        // ---- input window: 16 ic x 10x10 (stride 12), zero pad, fused GN+ReLU
        for (int d = t; d < 1600; d += 256) {
            int ic = d / 100, r = d - ic * 100;
            int iy = r / 10, ix = r - iy * 10;
            int gy = h0 - 1 + iy, gx = w0 - 1 + ix;
            float v = 0.f;
            if ((unsigned)gy < (unsigned)H && (unsigned)gx < (unsigned)W) {
                v = x[(long)(n * 256 + ic0 + ic) * HW + gy * W + gx];
                if (gnflag) v = fmaxf(v * scl[ic0 + ic] + shb[ic0 + ic], 0.f);
            }
            xs[ic * 120 + iy * 12 + ix] = v;
        }
        // ---- weights: 64 oc x 144 taps, div-free, LDG.128 ----
        {
            const int oca = oc0 + woc;
            if (oca < OC) {
                const float4* src = reinterpret_cast<const float4*>(
                    wgt + (long)oca * 2304 + ic0 * 9 + wq * 36);
#pragma unroll
                for (int i = 0; i < 9; i++) {
                    float4 v = src[i];
                    float* wp = ws + (wq * 36 + i * 4) * 68 + woc;
                    wp[0]   = v.x;
                    wp[68]  = v.y;
                    wp[136] = v.z;
                    wp[204] = v.w;
                }
            } else {
#pragma unroll
                for (int i = 0; i < 36; i++) ws[(wq * 36 + i) * 68 + woc] = 0.f;
            }
        }
        __syncthreads();

        const float* xbase = xs + ph * 12 + pw0;
        const float* wbase = ws + (oc_id << 2);
#pragma unroll 8
        for (int ic = 0; ic < 16; ic++) {
#pragma unroll
            for (int ky = 0; ky < 3; ky++) {
                const float* row = xbase + ic * 120 + ky * 12;
                float4 a4 = *reinterpret_cast<const float4*>(row);
                float2 b2 = *reinterpret_cast<const float2*>(row + 4);
                float xv[6] = {a4.x, a4.y, a4.z, a4.w, b2.x, b2.y};
#pragma unroll
                for (int kx = 0; kx < 3; kx++) {
                    const float4 wv = *reinterpret_cast<const float4*>(
                        wbase + (ic * 9 + ky * 3 + kx) * 68);
#pragma unroll
                    for (int j = 0; j < 4; j++) {
                        acc[0][j] += wv.x * xv[kx + j];
                        acc[1][j] += wv.y * xv[kx + j];
                        acc[2][j] += wv.z * xv[kx + j];
                        acc[3][j] += wv.w * xv[kx + j];
                    }
                }
            }
        }
        __syncthreads();
    }

    // ---- epilogue ----
    const int h = h0 + ph;
    if (h < H) {
        float* y = (ymode == 0) ? tb(br * 2 + ypp) + c_lb[l]
                 : (ymode == 2) ? g_reg + c_regoff[l] : nullptr;
#pragma unroll
        for (int i = 0; i < 4; i++) {
            int oc = oc0 + (oc_id << 2) + i;
            if (oc < OC) {
                float bv = bias[oc];
#pragma unroll
                for (int j = 0; j < 4; j++) {
                    int w = w0 + pw0 + j;
                    if (w < W) {
                        float v = acc[i][j] + bv;
                        if (ymode == 1) {
                            if (v > -3.0f) emit_cand(v, oc, h * W + w, n, l);
                        } else if (ymode == 0) {
                            y[(long)(n * 256 + oc) * HW + h * W + w] = v;
                        } else {
                            y[(long)(n * 36 + oc) * HW + h * W + w] = v;
                        }
                    }
                }
            }
        }
    }
}

// ------------------------- merged GroupNorm stats ---------------------------
__global__ __launch_bounds__(256) void gn_stats_m(int pp)
{
    int b = blockIdx.x;
    const int g = b % 32; b /= 32;
    const int n = b % 2;  b /= 2;
    const int l = b % 5;  b /= 5;
    const int br = b;
    const int HW = c_HW[l];
    const float* p = tb(br * 2 + pp) + c_lb[l] + (long)(n * 256 + g * 8) * HW;
    const int total = 8 * HW;
    double s = 0.0, ss = 0.0;
    for (int i = threadIdx.x; i < total; i += 256) {
        float v = p[i];
        s += v; ss += (double)v * (double)v;
    }
    __shared__ double rs[256], rq[256];
    rs[threadIdx.x] = s; rq[threadIdx.x] = ss;
    __syncthreads();
    for (int o = 128; o; o >>= 1) {
        if (threadIdx.x < o) { rs[threadIdx.x] += rs[threadIdx.x+o]; rq[threadIdx.x] += rq[threadIdx.x+o]; }
        __syncthreads();
    }
    if (threadIdx.x == 0) {
        int m = ((br * 5 + l) * 2 + n) * 32 + g;
        double mu = rs[0] / total;
        g_mu[m]  = (float)mu;
        g_var[m] = (float)(rq[0] / total - mu * mu);
    }
}

// ------------------------- sort / nms ----------------------------------------
__global__ void zero_cnt() { if (threadIdx.x < 10) g_cnt[threadIdx.x] = 0; }

__global__ __launch_bounds__(1024) void sort_k()
{
    const int b = blockIdx.x;
    ull* v = g_k64 + (long)b * CAPL;
    int cnt = g_cnt[b]; if (cnt > CAPL) cnt = CAPL;
    if (cnt <= 1) return;
    int n2 = 1; while (n2 < cnt) n2 <<= 1;
    for (int i = cnt + threadIdx.x; i < n2; i += 1024) v[i] = ~0ull;
    __syncthreads();
    for (int k = 2; k <= n2; k <<= 1) {
        for (int j = k >> 1; j > 0; j >>= 1) {
            for (int i = threadIdx.x; i < n2; i += 1024) {
                int ixj = i ^ j;
                if (ixj > i) {
                    ull a = v[i], c2 = v[ixj];
                    if ((a > c2) == ((i & k) == 0)) { v[i] = c2; v[ixj] = a; }
                }
            }
            __syncthreads();
        }
    }
}

extern __shared__ unsigned char s_raw[];

__global__ __launch_bounds__(256) void nms_k(const float* __restrict__ anc,
                                             float* __restrict__ out)
{
    const int n = blockIdx.x;
    float*    sws  = (float*)s_raw;
    float*    sbo  = (float*)s_raw + 5008;
    unsigned* skey = (unsigned*)((float*)s_raw + 25008);
    __shared__ float rbs[256];
    __shared__ unsigned rbk[256];
    __shared__ int rbi[256];

    int Ls[5], offs[5], K = 0;
    for (int l = 0; l < 5; l++) {
        int c = g_cnt[n * 5 + l];
        if (c > CAPL) c = CAPL;
        if (c > 1000) c = 1000;
        offs[l] = K; Ls[l] = c; K += c;
    }

    for (int idx = threadIdx.x; idx < K; idx += 256) {
        int l = 0;
        while (l < 4 && idx >= offs[l] + Ls[l]) l++;
        int kin = idx - offs[l];
        ull v = g_k64[(long)(n * 5 + l) * CAPL + kin];
        unsigned key = (unsigned)v;
        float sc = __uint_as_float(0xFFFFFFFFu - (unsigned)(v >> 32));
        int flat = (int)(key & 0xFFFFFFu);
        int ai = flat / 91, c = flat - ai * 91;
        int sidx = ai / 9, a = ai - sidx * 9;
        int HW = c_HW[l];
        const float* rp = g_reg + c_regoff[l] + (long)(n * 36 + a * 4) * HW + sidx;
        float dx = rp[0], dy = rp[HW], dw = rp[2*HW], dh = rp[3*HW];
        int gidx = c_ancoff[l] + ai;
        float ax0 = anc[4*gidx], ay0 = anc[4*gidx+1], ax1 = anc[4*gidx+2], ay1 = anc[4*gidx+3];
        float aw = ax1 - ax0, ah = ay1 - ay0;
        float cx = ax0 + 0.5f * aw, cy = ay0 + 0.5f * ah;
        dw = fminf(dw, BBOXCL); dh = fminf(dh, BBOXCL);
        float pcx = dx * aw + cx, pcy = dy * ah + cy;
        float pw = expf(dw) * aw, phh = expf(dh) * ah;
        float b0 = fminf(fmaxf(pcx - 0.5f*pw , 0.f), 1216.f);
        float b1 = fminf(fmaxf(pcy - 0.5f*phh, 0.f),  800.f);
        float b2 = fminf(fmaxf(pcx + 0.5f*pw , 0.f), 1216.f);
        float b3 = fminf(fmaxf(pcy + 0.5f*phh, 0.f),  800.f);
        float* nb = &g_nbox[(n * NMSCAP + idx) * 4];
        nb[0]=b0; nb[1]=b1; nb[2]=b2; nb[3]=b3;
        float off = (float)c * 2017.0f;
        sbo[idx*4+0]=b0+off; sbo[idx*4+1]=b1+off; sbo[idx*4+2]=b2+off; sbo[idx*4+3]=b3+off;
        sws[idx] = sc; skey[idx] = key;
    }
    __syncthreads();

    int m = 0;
    for (; m < 300; m++) {
        float bs = -1e30f; unsigned bk = 0xFFFFFFFFu; int bi = -1;
        for (int k = threadIdx.x; k < K; k += 256) {
            float s = sws[k];
            if (s > bs || (s == bs && skey[k] < bk)) { bs = s; bk = skey[k]; bi = k; }
        }
        rbs[threadIdx.x]=bs; rbk[threadIdx.x]=bk; rbi[threadIdx.x]=bi;
        __syncthreads();
        for (int o = 128; o; o >>= 1) {
            if (threadIdx.x < o) {
                float s2 = rbs[threadIdx.x+o];
                if (s2 > rbs[threadIdx.x] ||
                    (s2 == rbs[threadIdx.x] && rbk[threadIdx.x+o] < rbk[threadIdx.x])) {
                    rbs[threadIdx.x]=s2; rbk[threadIdx.x]=rbk[threadIdx.x+o]; rbi[threadIdx.x]=rbi[threadIdx.x+o];
                }
            }
            __syncthreads();
        }
        bs = rbs[0]; bi = rbi[0]; bk = rbk[0];
        if (bs <= 0.0f) break;
        if (threadIdx.x == 0) {
            float* nb = &g_nbox[(n * NMSCAP + bi) * 4];
            out[n*1200 + m*4+0]=nb[0]; out[n*1200 + m*4+1]=nb[1];
            out[n*1200 + m*4+2]=nb[2]; out[n*1200 + m*4+3]=nb[3];
            out[2400 + n*300 + m] = bs;
            out[3000 + n*300 + m] = (float)((bk & 0xFFFFFFu) % 91u);
        }
        float jb0=sbo[bi*4+0], jb1=sbo[bi*4+1], jb2=sbo[bi*4+2], jb3=sbo[bi*4+3];
        float ja = (jb2-jb0)*(jb3-jb1);
        for (int k = threadIdx.x; k < K; k += 256) {
            float x0 = fmaxf(jb0, sbo[k*4+0]);
            float y0 = fmaxf(jb1, sbo[k*4+1]);
            float x1 = fminf(jb2, sbo[k*4+2]);
            float y1 = fminf(jb3, sbo[k*4+3]);
            float iw = fmaxf(x1-x0, 0.f), ih = fmaxf(y1-y0, 0.f);
            float inter = iw*ih;
            float a2 = (sbo[k*4+2]-sbo[k*4+0])*(sbo[k*4+3]-sbo[k*4+1]);
            if (inter / (ja + a2 - inter + 1e-9f) > 0.5f) sws[k] = NEGV;
        }
        __syncthreads();
    }
    for (int slot = m + (int)threadIdx.x; slot < 300; slot += 256) {
        out[n*1200 + slot*4+0]=0.f; out[n*1200 + slot*4+1]=0.f;
        out[n*1200 + slot*4+2]=0.f; out[n*1200 + slot*4+3]=0.f;
        out[2400 + n*300 + slot] = 0.f;
        out[3000 + n*300 + slot] = -1.f;
    }
}

// ------------------------- host ----------------------------------------------
extern "C" void kernel_launch(void* const* d_in, const int* in_sizes, int n_in,
                              void* d_out, int out_size)
{
    const float* f0 = (const float*)d_in[0];
    const float* f1 = (const float*)d_in[1];
    const float* f2 = (const float*)d_in[2];
    const float* f3 = (const float*)d_in[3];
    const float* f4 = (const float*)d_in[4];
    const float* cls_tw = (const float*)d_in[5];
    const float* cls_tb = (const float*)d_in[6];
    const float* cls_gs = (const float*)d_in[7];
    const float* cls_gb = (const float*)d_in[8];
    const float* cls_w  = (const float*)d_in[9];
    const float* cls_b  = (const float*)d_in[10];
    const float* reg_tw = (const float*)d_in[11];
    const float* reg_tb = (const float*)d_in[12];
    const float* reg_gs = (const float*)d_in[13];
    const float* reg_gb = (const float*)d_in[14];
    const float* reg_w  = (const float*)d_in[15];
    const float* reg_b  = (const float*)d_in[16];
    const float* anchors = (const float*)d_in[17];
    float* out = (float*)d_out;

    const long TW1 = 589824; // 256*256*9
    cudaFuncSetAttribute(nms_k, cudaFuncAttributeMaxDynamicSharedMemorySize, 122880);

    zero_cnt<<<1, 32>>>();

    const int GT = 345 * 2 * 4 * 2;

    conv_m<<<GT, 256>>>(f0, f1, f2, f3, f4, -1, 0, 0,
                        cls_tw, reg_tw, cls_tb, reg_tb,
                        nullptr, nullptr, nullptr, nullptr,
                        0, 256, 4, 2, 0);
    gn_stats_m<<<640, 256>>>(0);
    conv_m<<<GT, 256>>>(nullptr, nullptr, nullptr, nullptr, nullptr, 0, 0, 1,
                        cls_tw + TW1, reg_tw + TW1, cls_tb + 256, reg_tb + 256,
                        cls_gs, cls_gb, reg_gs, reg_gb,
                        1, 256, 4, 2, 0);
    gn_stats_m<<<640, 256>>>(1);
    conv_m<<<GT, 256>>>(nullptr, nullptr, nullptr, nullptr, nullptr, 1, 0, 0,
                        cls_tw + 2*TW1, reg_tw + 2*TW1, cls_tb + 512, reg_tb + 512,
                        cls_gs + 256, cls_gb + 256, reg_gs + 256, reg_gb + 256,
                        1, 256, 4, 2, 0);
    gn_stats_m<<<640, 256>>>(0);
    conv_m<<<GT, 256>>>(nullptr, nullptr, nullptr, nullptr, nullptr, 0, 0, 1,
                        cls_tw + 3*TW1, reg_tw + 3*TW1, cls_tb + 768, reg_tb + 768,
                        cls_gs + 512, cls_gb + 512, reg_gs + 512, reg_gb + 512,
                        1, 256, 4, 2, 0);
    gn_stats_m<<<640, 256>>>(1);

    conv_m<<<345 * 2 * 13, 256>>>(nullptr, nullptr, nullptr, nullptr, nullptr, 1, 1, 0,
                        cls_w, cls_w, cls_b, cls_b,
                        cls_gs + 768, cls_gb + 768, cls_gs + 768, cls_gb + 768,
                        1, 819, 13, 1, 0);
    conv_m<<<345 * 2 * 1, 256>>>(nullptr, nullptr, nullptr, nullptr, nullptr, 1, 2, 0,
                        reg_w, reg_w, reg_b, reg_b,
                        reg_gs + 768, reg_gb + 768, reg_gs + 768, reg_gb + 768,
                        1, 36, 1, 1, 1);

    sort_k<<<10, 1024>>>();
    nms_k<<<2, 256, 122880>>>(anchors, out);
}